// round 15
// baseline (speedup 1.0000x reference)
#include <cuda_runtime.h>
#include <cstddef>
#include <cstdint>

#define HH 16
#define DD 1024
#define KD 64
#define NN 4096
#define MM 4096

static __device__ float g_Q[(size_t)HH * NN * KD];
static __device__ float g_K[(size_t)HH * MM * KD];
static __device__ float g_V[(size_t)HH * MM * KD];
static __device__ float g_O[(size_t)NN * (HH * KD)];
static __device__ unsigned g_mbits[(size_t)NN * (MM / 32)];

// ---- tf32 helpers (legacy mma.sync path: plain sm_80+ PTX) -----------------
__device__ __forceinline__ float tf32hi(float x) {
    float r; asm("cvt.rna.tf32.f32 %0, %1;" : "=f"(r) : "f"(x)); return r;
}
__device__ __forceinline__ void mma1688(float* d, const unsigned* a, const unsigned* b) {
    asm volatile(
        "mma.sync.aligned.m16n8k8.row.col.f32.tf32.tf32.f32 "
        "{%0,%1,%2,%3}, {%4,%5,%6,%7}, {%8,%9}, {%0,%1,%2,%3};"
        : "+f"(d[0]), "+f"(d[1]), "+f"(d[2]), "+f"(d[3])
        : "r"(a[0]), "r"(a[1]), "r"(a[2]), "r"(a[3]), "r"(b[0]), "r"(b[1]));
}

// ---------------------------------------------------------------------------
__global__ __launch_bounds__(256) void pack_mask(const int* __restrict__ mask,
                                                 unsigned* __restrict__ bits)
{
    int idx = blockIdx.x * 256 + threadIdx.x;
    const int* p = mask + (size_t)idx * 32;
    unsigned b = 0;
#pragma unroll
    for (int u = 0; u < 8; u++) {
        int4 m = ((const int4*)p)[u];
        b |= (unsigned)(m.x != 0) << (u * 4 + 0);
        b |= (unsigned)(m.y != 0) << (u * 4 + 1);
        b |= (unsigned)(m.z != 0) << (u * 4 + 2);
        b |= (unsigned)(m.w != 0) << (u * 4 + 3);
    }
    bits[idx] = b;
}

// ---------------------------------------------------------------------------
// tf32x3 mma.sync GEMM, frag-vectorized smem:
// Ahl[row][2k] = {hi,lo} interleaved, stride 72  (pair-bank coef 4: conflict-free)
// Bhl[k][2n]  = {hi,lo} interleaved, stride 136 (pair-bank coef 4: conflict-free)
// Every frag (hi+lo) pair = one LDS.64: 16 LDS.64 + 24 MMA per k8 step.
// ---------------------------------------------------------------------------
__global__ __launch_bounds__(256) void tmma33(
    const float* __restrict__ A, int lda,
    const float* __restrict__ W, long wStride, int ldw,
    float* __restrict__ C, long cStride, int ldc, int K)
{
    extern __shared__ float smf[];
    float* Ahl = smf;                 // 128 * 72
    float* Bhl = Ahl + 128 * 72;      // 32 * 136

    const int tid  = threadIdx.x;
    const int wid  = tid >> 5;
    const int lane = tid & 31;
    const int wm   = wid & 3;
    const int wn   = wid >> 2;
    const int m0   = wm * 32;
    const int n0   = wn * 32;
    const int gr   = lane >> 2;
    const int gc   = lane & 3;
    const int row0 = blockIdx.x * 128;
    const float* Wp = W + (long)blockIdx.y * wStride;
    float*       Cp = C + (long)blockIdx.y * cStride;

    float acc[2][4][4];
#pragma unroll
    for (int i = 0; i < 2; i++)
#pragma unroll
        for (int j = 0; j < 4; j++)
#pragma unroll
            for (int e = 0; e < 4; e++) acc[i][j][e] = 0.0f;

    for (int kt = 0; kt < K; kt += 32) {
        float4 aP[4], bP[2];
#pragma unroll
        for (int u = 0; u < 4; u++) {
            int idx = tid + u * 256;
            int r = idx >> 3, kv = idx & 7;
            aP[u] = *(const float4*)(A + (size_t)(row0 + r) * lda + kt + kv * 4);
        }
#pragma unroll
        for (int u = 0; u < 2; u++) {
            int idx = tid + u * 256;
            int kk = idx >> 4, nv = idx & 15;
            bP[u] = *(const float4*)(Wp + (size_t)(kt + kk) * ldw + nv * 4);
        }
        __syncthreads();

        // Split + store interleaved {hi,lo}
#pragma unroll
        for (int u = 0; u < 4; u++) {
            int idx = tid + u * 256;
            int r = idx >> 3, kv = idx & 7;
            float4 a = aP[u];
            float hx = tf32hi(a.x), hy = tf32hi(a.y), hz = tf32hi(a.z), hw = tf32hi(a.w);
            float* d = Ahl + r * 72 + 8 * kv;
            ((float4*)d)[0] = make_float4(hx, tf32hi(a.x - hx), hy, tf32hi(a.y - hy));
            ((float4*)d)[1] = make_float4(hz, tf32hi(a.z - hz), hw, tf32hi(a.w - hw));
        }
#pragma unroll
        for (int u = 0; u < 2; u++) {
            int idx = tid + u * 256;
            int kk = idx >> 4, nv = idx & 15;
            float4 b = bP[u];
            float hx = tf32hi(b.x), hy = tf32hi(b.y), hz = tf32hi(b.z), hw = tf32hi(b.w);
            float* d = Bhl + kk * 136 + 8 * nv;
            ((float4*)d)[0] = make_float4(hx, tf32hi(b.x - hx), hy, tf32hi(b.y - hy));
            ((float4*)d)[1] = make_float4(hz, tf32hi(b.z - hz), hw, tf32hi(b.w - hw));
        }
        __syncthreads();

#pragma unroll
        for (int s = 0; s < 4; s++) {
            const int k0 = s * 8;
            unsigned ah[2][4], al[2][4];
#pragma unroll
            for (int i = 0; i < 2; i++)
#pragma unroll
                for (int cs = 0; cs < 2; cs++)
#pragma unroll
                    for (int rs = 0; rs < 2; rs++) {
                        float2 hl = *(const float2*)(Ahl + (m0 + i * 16 + rs * 8 + gr) * 72
                                                     + 2 * (k0 + gc + 4 * cs));
                        ah[i][rs + 2 * cs] = __float_as_uint(hl.x);
                        al[i][rs + 2 * cs] = __float_as_uint(hl.y);
                    }
            unsigned bh[4][2], bl[4][2];
#pragma unroll
            for (int j = 0; j < 4; j++)
#pragma unroll
                for (int t = 0; t < 2; t++) {
                    float2 hl = *(const float2*)(Bhl + (k0 + gc + 4 * t) * 136
                                                 + 2 * (n0 + 8 * j + gr));
                    bh[j][t] = __float_as_uint(hl.x);
                    bl[j][t] = __float_as_uint(hl.y);
                }
#pragma unroll
            for (int i = 0; i < 2; i++)
#pragma unroll
                for (int j = 0; j < 4; j++) {
                    mma1688(acc[i][j], ah[i], bh[j]);
                    mma1688(acc[i][j], ah[i], bl[j]);
                    mma1688(acc[i][j], al[i], bh[j]);
                }
        }
        __syncthreads();
    }

#pragma unroll
    for (int i = 0; i < 2; i++) {
        int row = row0 + m0 + i * 16 + gr;
#pragma unroll
        for (int j = 0; j < 4; j++) {
            int col = n0 + j * 8 + 2 * gc;
            *(float2*)(Cp + (size_t)row * ldc + col) =
                make_float2(acc[i][j][0], acc[i][j][1]);
            *(float2*)(Cp + (size_t)(row + 8) * ldc + col) =
                make_float2(acc[i][j][2], acc[i][j][3]);
        }
    }
}

// ---------------------------------------------------------------------------
// Tensor-core flash attention, frag-vectorized:
// Khl[key][2kd] interleaved {hi,lo}, stride 136 -> K frags via LDS.64.
// Vhl[vd][2key'] interleaved, stride 72, XOR swizzle key' = key ^ ((vd>>2)&15)
// (conflict-free transposed stores AND frag loads) -> V frags via LDS.64.
// Q raw in smem, split per s (proven); P via smem (proven R13 math).
// ---------------------------------------------------------------------------
__global__ __launch_bounds__(256, 2) void attn_mma(void)
{
    extern __shared__ float smf[];
    float* Qs  = smf;                  // [128][68] raw f32
    float* Khl = Qs + 128 * 68;        // [32 key][136]
    float* Vhl = Khl + 32 * 136;       // [64 vd][72]
    float* Ps  = Vhl + 64 * 72;        // [128][36]

    const int tid  = threadIdx.x;
    const int wid  = tid >> 5;
    const int lane = tid & 31;
    const int gr   = lane >> 2;
    const int gc   = lane & 3;
    const int wm   = wid * 16;
    const int h    = blockIdx.x;
    const int nq0  = blockIdx.y * 128;

    const float* Qg = g_Q + (size_t)h * NN * KD;
    const float* Kg = g_K + (size_t)h * MM * KD;
    const float* Vg = g_V + (size_t)h * MM * KD;

#pragma unroll
    for (int u = 0; u < 8; u++) {
        int idx = tid + u * 256;
        int r = idx >> 4, kv = idx & 15;
        *(float4*)(Qs + r * 68 + kv * 4) =
            *(const float4*)(Qg + (size_t)(nq0 + r) * KD + kv * 4);
    }

    float mrow[2] = { -1e30f, -1e30f };
    float lrow[2] = { 0.0f, 0.0f };
    float oc[8][4];
#pragma unroll
    for (int n = 0; n < 8; n++)
#pragma unroll
        for (int e = 0; e < 4; e++) oc[n][e] = 0.0f;

    const int row0 = nq0 + wm + gr;

    for (int mt = 0; mt < MM; mt += 32) {
        __syncthreads();               // prior tile's readers done

        // Stage K (interleaved) + V (transposed, swizzled, interleaved)
#pragma unroll
        for (int u = 0; u < 2; u++) {
            int idx = tid + u * 256;
            int key = idx >> 4, kv = idx & 15;
            float4 k4 = *(const float4*)(Kg + (size_t)(mt + key) * KD + kv * 4);
            float hx = tf32hi(k4.x), hy = tf32hi(k4.y), hz = tf32hi(k4.z), hw = tf32hi(k4.w);
            float* kd_ = Khl + key * 136 + 8 * kv;
            ((float4*)kd_)[0] = make_float4(hx, tf32hi(k4.x - hx), hy, tf32hi(k4.y - hy));
            ((float4*)kd_)[1] = make_float4(hz, tf32hi(k4.z - hz), hw, tf32hi(k4.w - hw));

            float4 v4 = *(const float4*)(Vg + (size_t)(mt + key) * KD + kv * 4);
            int keyx = 2 * (key ^ kv);         // swizzle: (vd>>2)&15 == kv for vd=4kv+e
            float vh;
            vh = tf32hi(v4.x);
            *(float2*)(Vhl + (4 * kv + 0) * 72 + keyx) = make_float2(vh, tf32hi(v4.x - vh));
            vh = tf32hi(v4.y);
            *(float2*)(Vhl + (4 * kv + 1) * 72 + keyx) = make_float2(vh, tf32hi(v4.y - vh));
            vh = tf32hi(v4.z);
            *(float2*)(Vhl + (4 * kv + 2) * 72 + keyx) = make_float2(vh, tf32hi(v4.z - vh));
            vh = tf32hi(v4.w);
            *(float2*)(Vhl + (4 * kv + 3) * 72 + keyx) = make_float2(vh, tf32hi(v4.w - vh));
        }

        const unsigned mw0 = g_mbits[(size_t)row0 * (MM / 32) + (mt >> 5)];
        const unsigned mw1 = g_mbits[(size_t)(row0 + 8) * (MM / 32) + (mt >> 5)];
        __syncthreads();

        // ---- S = Q K^T (tf32 x3; Q split per s, K frags LDS.64) ----
        float sc[4][4];
#pragma unroll
        for (int j = 0; j < 4; j++)
#pragma unroll
            for (int e = 0; e < 4; e++) sc[j][e] = 0.0f;

#pragma unroll
        for (int s = 0; s < 8; s++) {
            const int k0 = s * 8;
            const float* Qr = Qs + (wm + gr) * 68 + k0 + gc;
            float f0 = Qr[0], f1 = Qr[8 * 68], f2 = Qr[4], f3 = Qr[8 * 68 + 4];
            float h0 = tf32hi(f0), h1 = tf32hi(f1), h2 = tf32hi(f2), h3 = tf32hi(f3);
            unsigned qh[4] = { __float_as_uint(h0), __float_as_uint(h1),
                               __float_as_uint(h2), __float_as_uint(h3) };
            unsigned ql[4] = { __float_as_uint(tf32hi(f0 - h0)), __float_as_uint(tf32hi(f1 - h1)),
                               __float_as_uint(tf32hi(f2 - h2)), __float_as_uint(tf32hi(f3 - h3)) };
#pragma unroll
            for (int j = 0; j < 4; j++) {
                const float* kr = Khl + (8 * j + gr) * 136;
                float2 p0 = *(const float2*)(kr + 2 * (k0 + gc));
                float2 p1 = *(const float2*)(kr + 2 * (k0 + gc + 4));
                unsigned bh[2] = { __float_as_uint(p0.x), __float_as_uint(p1.x) };
                unsigned bl[2] = { __float_as_uint(p0.y), __float_as_uint(p1.y) };
                mma1688(sc[j], qh, bh);
                mma1688(sc[j], qh, bl);
                mma1688(sc[j], ql, bh);
            }
        }

        // ---- mask + online softmax (unchanged R13 math) ----
        float scl[2];
#pragma unroll
        for (int e = 0; e < 2; e++) {
            const unsigned w = e ? mw1 : mw0;
            float v[8];
#pragma unroll
            for (int j = 0; j < 4; j++) {
                v[2 * j]     = sc[j][2 * e];
                v[2 * j + 1] = sc[j][2 * e + 1];
                unsigned b2 = (w >> (8 * j + 2 * gc)) & 3u;
                if (!(b2 & 1u)) v[2 * j]     = -1e30f;
                if (!(b2 & 2u)) v[2 * j + 1] = -1e30f;
            }
            float mx = fmaxf(fmaxf(fmaxf(v[0], v[1]), fmaxf(v[2], v[3])),
                             fmaxf(fmaxf(v[4], v[5]), fmaxf(v[6], v[7])));
            mx = fmaxf(mx, __shfl_xor_sync(0xffffffffu, mx, 1));
            mx = fmaxf(mx, __shfl_xor_sync(0xffffffffu, mx, 2));
            float mnew = fmaxf(mrow[e], mx);
            scl[e] = __expf(mrow[e] - mnew);
            mrow[e] = mnew;
            float rs = 0.0f;
#pragma unroll
            for (int t = 0; t < 8; t++) {
                float p = tf32hi(__expf(v[t] - mnew));   // round BEFORE summing
                v[t] = p;
                rs += p;
            }
            rs += __shfl_xor_sync(0xffffffffu, rs, 1);
            rs += __shfl_xor_sync(0xffffffffu, rs, 2);
            lrow[e] = lrow[e] * scl[e] + rs;
#pragma unroll
            for (int j = 0; j < 4; j++) {
                sc[j][2 * e]     = v[2 * j];
                sc[j][2 * e + 1] = v[2 * j + 1];
            }
        }
#pragma unroll
        for (int n = 0; n < 8; n++) {
            oc[n][0] *= scl[0]; oc[n][1] *= scl[0];
            oc[n][2] *= scl[1]; oc[n][3] *= scl[1];
        }
        {
            float* Pr0 = Ps + (wm + gr) * 36;
            float* Pr1 = Ps + (wm + gr + 8) * 36;
#pragma unroll
            for (int j = 0; j < 4; j++) {
                *(float2*)(Pr0 + 8 * j + 2 * gc) = make_float2(sc[j][0], sc[j][1]);
                *(float2*)(Pr1 + 8 * j + 2 * gc) = make_float2(sc[j][2], sc[j][3]);
            }
        }
        __syncwarp();

        // ---- O += P V (P tf32; V frags LDS.64 from swizzled layout) ----
#pragma unroll
        for (int kc = 0; kc < 4; kc++) {
            const int k0 = kc * 8;
            int pb = (wm + gr) * 36 + k0 + gc;
            unsigned pa[4] = { __float_as_uint(Ps[pb]),
                               __float_as_uint(Ps[pb + 8 * 36]),
                               __float_as_uint(Ps[pb + 4]),
                               __float_as_uint(Ps[pb + 8 * 36 + 4]) };
#pragma unroll
            for (int n = 0; n < 8; n++) {
                const int vd  = n * 8 + gr;
                const int swz = (vd >> 2) & 15;
                const float* vr = Vhl + vd * 72;
                float2 p0 = *(const float2*)(vr + 2 * ((k0 + gc) ^ swz));
                float2 p1 = *(const float2*)(vr + 2 * ((k0 + gc + 4) ^ swz));
                unsigned bvh[2] = { __float_as_uint(p0.x), __float_as_uint(p1.x) };
                unsigned bvl[2] = { __float_as_uint(p0.y), __float_as_uint(p1.y) };
                mma1688(oc[n], pa, bvh);
                mma1688(oc[n], pa, bvl);
            }
        }
    }

    const float i0 = 1.0f / lrow[0];
    const float i1 = 1.0f / lrow[1];
    float* ob = g_O + (size_t)row0 * (HH * KD) + h * KD;
#pragma unroll
    for (int n = 0; n < 8; n++) {
        *(float2*)(ob + n * 8 + 2 * gc) =
            make_float2(oc[n][0] * i0, oc[n][1] * i0);
        *(float2*)(ob + (size_t)8 * (HH * KD) + n * 8 + 2 * gc) =
            make_float2(oc[n][2] * i1, oc[n][3] * i1);
    }
}

// ---------------------------------------------------------------------------
extern "C" void kernel_launch(void* const* d_in, const int* in_sizes, int n_in,
                              void* d_out, int out_size)
{
    const float* X    = (const float*)d_in[0];
    const float* Mm   = (const float*)d_in[1];
    const int*   mask = (const int*)  d_in[2];
    const float* Wq   = (const float*)d_in[3];
    const float* Wk   = (const float*)d_in[4];
    const float* Wv   = (const float*)d_in[5];
    const float* Wo   = (const float*)d_in[6];
    float*       Y    = (float*)d_out;

    float *qp, *kp, *vp, *op;
    unsigned* mbp;
    cudaGetSymbolAddress((void**)&qp, g_Q);
    cudaGetSymbolAddress((void**)&kp, g_K);
    cudaGetSymbolAddress((void**)&vp, g_V);
    cudaGetSymbolAddress((void**)&op, g_O);
    cudaGetSymbolAddress((void**)&mbp, g_mbits);

    // attn: Qs 8704 + Khl 4352 + Vhl 4608 + Ps 4608 = 22272 floats = 89088 B
    const int SMEM_AT = (128 * 68 + 32 * 136 + 64 * 72 + 128 * 36) * (int)sizeof(float);
    cudaFuncSetAttribute(attn_mma, cudaFuncAttributeMaxDynamicSharedMemorySize, SMEM_AT);
    // gemm: Ahl 9216 + Bhl 4352 = 13568 floats = 54272 B
    const int SMEM_TM = (128 * 72 + 32 * 136) * (int)sizeof(float);
    cudaFuncSetAttribute(tmma33, cudaFuncAttributeMaxDynamicSharedMemorySize, SMEM_TM);

    const long DK = (long)DD * KD, NK = (long)NN * KD, MK = (long)MM * KD;

    pack_mask<<<(NN * (MM / 32)) / 256, 256>>>(mask, mbp);
    tmma33<<<dim3(NN / 128, HH), 256, SMEM_TM>>>(X,  DD, Wq, DK, KD, qp, NK, KD, DD);
    tmma33<<<dim3(MM / 128, HH), 256, SMEM_TM>>>(Mm, DD, Wk, DK, KD, kp, MK, KD, DD);
    tmma33<<<dim3(MM / 128, HH), 256, SMEM_TM>>>(Mm, DD, Wv, DK, KD, vp, MK, KD, DD);
    attn_mma<<<dim3(HH, NN / 128), 256, SMEM_AT>>>();
    tmma33<<<dim3(NN / 128, (HH * KD) / 64), 256, SMEM_TM>>>(op, HH * KD, Wo, 64, HH * KD,
                                                             Y, 64, HH * KD, DD);
}

// round 16
// speedup vs baseline: 1.3658x; 1.3658x over previous
#include <cuda_runtime.h>
#include <cstddef>
#include <cstdint>

#define HH 16
#define DD 1024
#define KD 64
#define NN 4096
#define MM 4096

static __device__ float g_Q[(size_t)HH * NN * KD];
static __device__ float g_K[(size_t)HH * MM * KD];
static __device__ float g_V[(size_t)HH * MM * KD];
static __device__ float g_O[(size_t)NN * (HH * KD)];
static __device__ unsigned g_mbits[(size_t)NN * (MM / 32)];

// ---- tf32 helpers (legacy mma.sync path: plain sm_80+ PTX) -----------------
__device__ __forceinline__ float tf32hi(float x) {
    float r; asm("cvt.rna.tf32.f32 %0, %1;" : "=f"(r) : "f"(x)); return r;
}
__device__ __forceinline__ void mma1688(float* d, const unsigned* a, const unsigned* b) {
    asm volatile(
        "mma.sync.aligned.m16n8k8.row.col.f32.tf32.tf32.f32 "
        "{%0,%1,%2,%3}, {%4,%5,%6,%7}, {%8,%9}, {%0,%1,%2,%3};"
        : "+f"(d[0]), "+f"(d[1]), "+f"(d[2]), "+f"(d[3])
        : "r"(a[0]), "r"(a[1]), "r"(a[2]), "r"(a[3]), "r"(b[0]), "r"(b[1]));
}

// ---------------------------------------------------------------------------
__global__ __launch_bounds__(256) void pack_mask(const int* __restrict__ mask,
                                                 unsigned* __restrict__ bits)
{
    int idx = blockIdx.x * 256 + threadIdx.x;
    const int* p = mask + (size_t)idx * 32;
    unsigned b = 0;
#pragma unroll
    for (int u = 0; u < 8; u++) {
        int4 m = ((const int4*)p)[u];
        b |= (unsigned)(m.x != 0) << (u * 4 + 0);
        b |= (unsigned)(m.y != 0) << (u * 4 + 1);
        b |= (unsigned)(m.z != 0) << (u * 4 + 2);
        b |= (unsigned)(m.w != 0) << (u * 4 + 3);
    }
    bits[idx] = b;
}

// ---------------------------------------------------------------------------
// R13-proven tf32x3 GEMM body (scalar LDS frags, strides 36/72).
// ---------------------------------------------------------------------------
__device__ __forceinline__ void tmma_body(
    const float* A, int lda, const float* Wp, int ldw,
    float* Cp, int ldc, int K, int row0, float* smf)
{
    float* Ah = smf;
    float* Al = Ah + 128 * 36;
    float* Bh = Al + 128 * 36;
    float* Bl = Bh + 32 * 72;

    const int tid  = threadIdx.x;
    const int wid  = tid >> 5;
    const int lane = tid & 31;
    const int m0   = (wid & 3) * 32;
    const int n0   = (wid >> 2) * 32;
    const int gr   = lane >> 2;
    const int gc   = lane & 3;

    float acc[2][4][4];
#pragma unroll
    for (int i = 0; i < 2; i++)
#pragma unroll
        for (int j = 0; j < 4; j++)
#pragma unroll
            for (int e = 0; e < 4; e++) acc[i][j][e] = 0.0f;

    for (int kt = 0; kt < K; kt += 32) {
        float4 aP[4], bP[2];
#pragma unroll
        for (int u = 0; u < 4; u++) {
            int idx = tid + u * 256;
            int r = idx >> 3, kv = idx & 7;
            aP[u] = *(const float4*)(A + (size_t)(row0 + r) * lda + kt + kv * 4);
        }
#pragma unroll
        for (int u = 0; u < 2; u++) {
            int idx = tid + u * 256;
            int kk = idx >> 4, nv = idx & 15;
            bP[u] = *(const float4*)(Wp + (size_t)(kt + kk) * ldw + nv * 4);
        }
        __syncthreads();

#pragma unroll
        for (int u = 0; u < 4; u++) {
            int idx = tid + u * 256;
            int r = idx >> 3, kv = idx & 7;
            float4 a = aP[u];
            float4 h = make_float4(tf32hi(a.x), tf32hi(a.y), tf32hi(a.z), tf32hi(a.w));
            float4 l = make_float4(tf32hi(a.x - h.x), tf32hi(a.y - h.y),
                                   tf32hi(a.z - h.z), tf32hi(a.w - h.w));
            *(float4*)(Ah + r * 36 + kv * 4) = h;
            *(float4*)(Al + r * 36 + kv * 4) = l;
        }
#pragma unroll
        for (int u = 0; u < 2; u++) {
            int idx = tid + u * 256;
            int kk = idx >> 4, nv = idx & 15;
            float4 b = bP[u];
            float4 h = make_float4(tf32hi(b.x), tf32hi(b.y), tf32hi(b.z), tf32hi(b.w));
            float4 l = make_float4(tf32hi(b.x - h.x), tf32hi(b.y - h.y),
                                   tf32hi(b.z - h.z), tf32hi(b.w - h.w));
            *(float4*)(Bh + kk * 72 + nv * 4) = h;
            *(float4*)(Bl + kk * 72 + nv * 4) = l;
        }
        __syncthreads();

#pragma unroll
        for (int s = 0; s < 4; s++) {
            const int k0 = s * 8;
            unsigned ah[2][4], al[2][4];
#pragma unroll
            for (int i = 0; i < 2; i++) {
                int base = (m0 + i * 16 + gr) * 36 + k0 + gc;
                ah[i][0] = __float_as_uint(Ah[base]);
                ah[i][1] = __float_as_uint(Ah[base + 8 * 36]);
                ah[i][2] = __float_as_uint(Ah[base + 4]);
                ah[i][3] = __float_as_uint(Ah[base + 8 * 36 + 4]);
                al[i][0] = __float_as_uint(Al[base]);
                al[i][1] = __float_as_uint(Al[base + 8 * 36]);
                al[i][2] = __float_as_uint(Al[base + 4]);
                al[i][3] = __float_as_uint(Al[base + 8 * 36 + 4]);
            }
            unsigned bh[4][2], bl[4][2];
#pragma unroll
            for (int j = 0; j < 4; j++) {
                int base = (k0 + gc) * 72 + n0 + j * 8 + gr;
                bh[j][0] = __float_as_uint(Bh[base]);
                bh[j][1] = __float_as_uint(Bh[base + 4 * 72]);
                bl[j][0] = __float_as_uint(Bl[base]);
                bl[j][1] = __float_as_uint(Bl[base + 4 * 72]);
            }
#pragma unroll
            for (int i = 0; i < 2; i++)
#pragma unroll
                for (int j = 0; j < 4; j++) {
                    mma1688(acc[i][j], ah[i], bh[j]);
                    mma1688(acc[i][j], ah[i], bl[j]);
                    mma1688(acc[i][j], al[i], bh[j]);
                }
        }
        __syncthreads();
    }

#pragma unroll
    for (int i = 0; i < 2; i++) {
        int row = row0 + m0 + i * 16 + gr;
#pragma unroll
        for (int j = 0; j < 4; j++) {
            int col = n0 + j * 8 + 2 * gc;
            *(float2*)(Cp + (size_t)row * ldc + col) =
                make_float2(acc[i][j][0], acc[i][j][1]);
            *(float2*)(Cp + (size_t)(row + 8) * ldc + col) =
                make_float2(acc[i][j][2], acc[i][j][3]);
        }
    }
}

// Merged Q/K/V projection: one launch, grid (32, 48); y selects {Q,K,V} x head.
__global__ __launch_bounds__(256) void tmma_qkv(
    const float* __restrict__ X, const float* __restrict__ Mm,
    const float* __restrict__ Wq, const float* __restrict__ Wk,
    const float* __restrict__ Wv,
    float* qp, float* kp, float* vp)
{
    extern __shared__ float smf[];
    const int y    = blockIdx.y;
    const int grp  = y >> 4;          // 0=Q, 1=K, 2=V
    const int head = y & 15;
    const float* A = (grp == 0) ? X : Mm;
    const float* W = ((grp == 0) ? Wq : (grp == 1) ? Wk : Wv) + (size_t)head * DD * KD;
    float*       C = ((grp == 0) ? qp : (grp == 1) ? kp : vp) + (size_t)head * NN * KD;
    tmma_body(A, DD, W, KD, C, KD, DD, blockIdx.x * 128, smf);
}

// Generic panel GEMM (used for Y = O @ Wo).
__global__ __launch_bounds__(256) void tmma33(
    const float* __restrict__ A, int lda,
    const float* __restrict__ W, long wStride, int ldw,
    float* __restrict__ C, long cStride, int ldc, int K)
{
    extern __shared__ float smf[];
    tmma_body(A, lda, W + (long)blockIdx.y * wStride, ldw,
              C + (long)blockIdx.y * cStride, ldc, K, blockIdx.x * 128, smf);
}

// ---------------------------------------------------------------------------
// Tensor-core flash attention (R13 math) with:
//  - V single rounded tf32 (x1 PV; V rounding is common-mode on O, not
//    softmax-amplified) -> 20% fewer MMAs
//  - Ps aliased onto Kh/Kl (K dead after QK; extra barrier fences aliasing)
//  - smem 62 KB -> 3 CTAs/SM
// K strides 76 (banks 12gr+gc all-distinct). Everything else R13-proven.
// ---------------------------------------------------------------------------
__global__ __launch_bounds__(256, 3) void attn_mma(void)
{
    extern __shared__ float smf[];
    float* Qs = smf;                   // [128][68] raw f32
    float* Kh = Qs + 128 * 68;         // [32 key][76]
    float* Kl = Kh + 32 * 76;          // [32 key][76]
    float* Vs = Kl + 32 * 76;          // [32 key][72] rounded tf32
    float* Ps = Kh;                    // [128][36] ALIAS (K dead after QK)

    const int tid  = threadIdx.x;
    const int wid  = tid >> 5;
    const int lane = tid & 31;
    const int gr   = lane >> 2;
    const int gc   = lane & 3;
    const int wm   = wid * 16;
    const int h    = blockIdx.x;       // heads fastest -> K/V + mask L2 reuse
    const int nq0  = blockIdx.y * 128;

    const float* Qg = g_Q + (size_t)h * NN * KD;
    const float* Kg = g_K + (size_t)h * MM * KD;
    const float* Vg = g_V + (size_t)h * MM * KD;

#pragma unroll
    for (int u = 0; u < 8; u++) {
        int idx = tid + u * 256;
        int r = idx >> 4, kv = idx & 15;
        *(float4*)(Qs + r * 68 + kv * 4) =
            *(const float4*)(Qg + (size_t)(nq0 + r) * KD + kv * 4);
    }

    float mrow[2] = { -1e30f, -1e30f };
    float lrow[2] = { 0.0f, 0.0f };
    float oc[8][4];
#pragma unroll
    for (int n = 0; n < 8; n++)
#pragma unroll
        for (int e = 0; e < 4; e++) oc[n][e] = 0.0f;

    const int row0 = nq0 + wm + gr;

    for (int mt = 0; mt < MM; mt += 32) {
        __syncthreads();               // prior tile: PV reads of Ps/Vs done

        // Stage K (hi/lo, stride 76) + V (single rounded tf32, stride 72)
#pragma unroll
        for (int u = 0; u < 2; u++) {
            int idx = tid + u * 256;
            int key = idx >> 4, kv = idx & 15;
            float4 k4 = *(const float4*)(Kg + (size_t)(mt + key) * KD + kv * 4);
            float4 kh = make_float4(tf32hi(k4.x), tf32hi(k4.y), tf32hi(k4.z), tf32hi(k4.w));
            float4 kl = make_float4(tf32hi(k4.x - kh.x), tf32hi(k4.y - kh.y),
                                    tf32hi(k4.z - kh.z), tf32hi(k4.w - kh.w));
            *(float4*)(Kh + key * 76 + kv * 4) = kh;
            *(float4*)(Kl + key * 76 + kv * 4) = kl;
            float4 v4 = *(const float4*)(Vg + (size_t)(mt + key) * KD + kv * 4);
            *(float4*)(Vs + key * 72 + kv * 4) =
                make_float4(tf32hi(v4.x), tf32hi(v4.y), tf32hi(v4.z), tf32hi(v4.w));
        }

        const unsigned mw0 = g_mbits[(size_t)row0 * (MM / 32) + (mt >> 5)];
        const unsigned mw1 = g_mbits[(size_t)(row0 + 8) * (MM / 32) + (mt >> 5)];
        __syncthreads();

        // ---- S = Q K^T (tf32 x3; Q split per s) ----
        float sc[4][4];
#pragma unroll
        for (int j = 0; j < 4; j++)
#pragma unroll
            for (int e = 0; e < 4; e++) sc[j][e] = 0.0f;

#pragma unroll
        for (int s = 0; s < 8; s++) {
            const int k0 = s * 8;
            const float* Qr = Qs + (wm + gr) * 68 + k0 + gc;
            float f0 = Qr[0], f1 = Qr[8 * 68], f2 = Qr[4], f3 = Qr[8 * 68 + 4];
            float h0 = tf32hi(f0), h1 = tf32hi(f1), h2 = tf32hi(f2), h3 = tf32hi(f3);
            unsigned qh[4] = { __float_as_uint(h0), __float_as_uint(h1),
                               __float_as_uint(h2), __float_as_uint(h3) };
            unsigned ql[4] = { __float_as_uint(tf32hi(f0 - h0)), __float_as_uint(tf32hi(f1 - h1)),
                               __float_as_uint(tf32hi(f2 - h2)), __float_as_uint(tf32hi(f3 - h3)) };
#pragma unroll
            for (int j = 0; j < 4; j++) {
                int kb = (j * 8 + gr) * 76 + k0 + gc;
                unsigned bh[2] = { __float_as_uint(Kh[kb]), __float_as_uint(Kh[kb + 4]) };
                unsigned bl[2] = { __float_as_uint(Kl[kb]), __float_as_uint(Kl[kb + 4]) };
                mma1688(sc[j], qh, bh);
                mma1688(sc[j], qh, bl);
                mma1688(sc[j], ql, bh);
            }
        }
        __syncthreads();               // QK reads of Kh/Kl done: Ps may overwrite

        // ---- mask + online softmax (R13 math) ----
        float scl[2];
#pragma unroll
        for (int e = 0; e < 2; e++) {
            const unsigned w = e ? mw1 : mw0;
            float v[8];
#pragma unroll
            for (int j = 0; j < 4; j++) {
                v[2 * j]     = sc[j][2 * e];
                v[2 * j + 1] = sc[j][2 * e + 1];
                unsigned b2 = (w >> (8 * j + 2 * gc)) & 3u;
                if (!(b2 & 1u)) v[2 * j]     = -1e30f;
                if (!(b2 & 2u)) v[2 * j + 1] = -1e30f;
            }
            float mx = fmaxf(fmaxf(fmaxf(v[0], v[1]), fmaxf(v[2], v[3])),
                             fmaxf(fmaxf(v[4], v[5]), fmaxf(v[6], v[7])));
            mx = fmaxf(mx, __shfl_xor_sync(0xffffffffu, mx, 1));
            mx = fmaxf(mx, __shfl_xor_sync(0xffffffffu, mx, 2));
            float mnew = fmaxf(mrow[e], mx);
            scl[e] = __expf(mrow[e] - mnew);
            mrow[e] = mnew;
            float rs = 0.0f;
#pragma unroll
            for (int t = 0; t < 8; t++) {
                float p = tf32hi(__expf(v[t] - mnew));   // round BEFORE summing
                v[t] = p;
                rs += p;
            }
            rs += __shfl_xor_sync(0xffffffffu, rs, 1);
            rs += __shfl_xor_sync(0xffffffffu, rs, 2);
            lrow[e] = lrow[e] * scl[e] + rs;
#pragma unroll
            for (int j = 0; j < 4; j++) {
                sc[j][2 * e]     = v[2 * j];
                sc[j][2 * e + 1] = v[2 * j + 1];
            }
        }
#pragma unroll
        for (int n = 0; n < 8; n++) {
            oc[n][0] *= scl[0]; oc[n][1] *= scl[0];
            oc[n][2] *= scl[1]; oc[n][3] *= scl[1];
        }
        {
            float* Pr0 = Ps + (wm + gr) * 36;
            float* Pr1 = Ps + (wm + gr + 8) * 36;
#pragma unroll
            for (int j = 0; j < 4; j++) {
                *(float2*)(Pr0 + 8 * j + 2 * gc) = make_float2(sc[j][0], sc[j][1]);
                *(float2*)(Pr1 + 8 * j + 2 * gc) = make_float2(sc[j][2], sc[j][3]);
            }
        }
        __syncwarp();                  // Ps rows are warp-private

        // ---- O += P V (V single tf32) ----
#pragma unroll
        for (int kc = 0; kc < 4; kc++) {
            const int k0 = kc * 8;
            int pb = (wm + gr) * 36 + k0 + gc;
            unsigned pa[4] = { __float_as_uint(Ps[pb]),
                               __float_as_uint(Ps[pb + 8 * 36]),
                               __float_as_uint(Ps[pb + 4]),
                               __float_as_uint(Ps[pb + 8 * 36 + 4]) };
#pragma unroll
            for (int n = 0; n < 8; n++) {
                int vb = (k0 + gc) * 72 + n * 8 + gr;
                unsigned bv[2] = { __float_as_uint(Vs[vb]), __float_as_uint(Vs[vb + 4 * 72]) };
                mma1688(oc[n], pa, bv);
            }
        }
    }

    const float i0 = 1.0f / lrow[0];
    const float i1 = 1.0f / lrow[1];
    float* ob = g_O + (size_t)row0 * (HH * KD) + h * KD;
#pragma unroll
    for (int n = 0; n < 8; n++) {
        *(float2*)(ob + n * 8 + 2 * gc) =
            make_float2(oc[n][0] * i0, oc[n][1] * i0);
        *(float2*)(ob + (size_t)8 * (HH * KD) + n * 8 + 2 * gc) =
            make_float2(oc[n][2] * i1, oc[n][3] * i1);
    }
}

// ---------------------------------------------------------------------------
extern "C" void kernel_launch(void* const* d_in, const int* in_sizes, int n_in,
                              void* d_out, int out_size)
{
    const float* X    = (const float*)d_in[0];
    const float* Mm   = (const float*)d_in[1];
    const int*   mask = (const int*)  d_in[2];
    const float* Wq   = (const float*)d_in[3];
    const float* Wk   = (const float*)d_in[4];
    const float* Wv   = (const float*)d_in[5];
    const float* Wo   = (const float*)d_in[6];
    float*       Y    = (float*)d_out;

    float *qp, *kp, *vp, *op;
    unsigned* mbp;
    cudaGetSymbolAddress((void**)&qp, g_Q);
    cudaGetSymbolAddress((void**)&kp, g_K);
    cudaGetSymbolAddress((void**)&vp, g_V);
    cudaGetSymbolAddress((void**)&op, g_O);
    cudaGetSymbolAddress((void**)&mbp, g_mbits);

    // attn: Qs 8704 + Kh/Kl 2*2432 + Vs 2304 = 15872 floats = 63488 B
    const int SMEM_AT = (128 * 68 + 2 * 32 * 76 + 32 * 72) * (int)sizeof(float);
    cudaFuncSetAttribute(attn_mma, cudaFuncAttributeMaxDynamicSharedMemorySize, SMEM_AT);
    const int SMEM_TM = (128 * 36 * 2 + 32 * 72 * 2) * (int)sizeof(float);
    cudaFuncSetAttribute(tmma33,   cudaFuncAttributeMaxDynamicSharedMemorySize, SMEM_TM);
    cudaFuncSetAttribute(tmma_qkv, cudaFuncAttributeMaxDynamicSharedMemorySize, SMEM_TM);

    pack_mask<<<(NN * (MM / 32)) / 256, 256>>>(mask, mbp);
    // Q, K, V projections in ONE launch (one wave-tail instead of three)
    tmma_qkv<<<dim3(NN / 128, 48), 256, SMEM_TM>>>(X, Mm, Wq, Wk, Wv, qp, kp, vp);
    attn_mma<<<dim3(HH, NN / 128), 256, SMEM_AT>>>();
    tmma33<<<dim3(NN / 128, (HH * KD) / 64), 256, SMEM_TM>>>(op, HH * KD, Wo, 64, HH * KD,
                                                             Y, 64, HH * KD, DD);
}